// round 1
// baseline (speedup 1.0000x reference)
#include <cuda_runtime.h>

// Problem constants
#define B_ 2
#define T_ 2048
#define E_ 1024
#define H_ 16
#define D_ 64
#define BT_ (B_ * T_)

// Scratch (allocation-free: __device__ globals)
__device__ float g_q[(size_t)B_ * H_ * T_ * D_];
__device__ float g_k[(size_t)B_ * H_ * T_ * D_];
__device__ float g_v[(size_t)B_ * H_ * T_ * D_];
__device__ float g_att[(size_t)BT_ * E_];

// ============================================================================
// Register-tiled SGEMM, C[m,n] = sum_k A[m,k] * Bmat[n,k]  (both K-major, "NT")
// BM=BN=128, BK=16, 8x8 per thread, 256 threads.
// MODE 0: A = Ain (x), scatter-store into g_q/g_k/g_v with [B,H,T,D] layout.
// MODE 1: A = g_att, plain store to C.
// ============================================================================
#define BM 128
#define BN 128
#define BK 16

template <int MODE, int N, int K>
__global__ void __launch_bounds__(256) sgemm_nt(const float* __restrict__ Ain,
                                                const float* __restrict__ Bmat,
                                                float* __restrict__ C) {
    __shared__ float As[BK][BM + 4];   // stride 132: 16B-aligned rows, transposed store
    __shared__ float Bs[BK][BN + 4];

    const float* A = (MODE == 0) ? Ain : g_att;

    const int tid = threadIdx.x;
    const int m0 = blockIdx.y * BM;
    const int n0 = blockIdx.x * BN;
    const int tx = tid & 15;   // n-dir
    const int ty = tid >> 4;   // m-dir

    float acc[8][8];
#pragma unroll
    for (int i = 0; i < 8; i++)
#pragma unroll
        for (int j = 0; j < 8; j++) acc[i][j] = 0.0f;

    for (int k0 = 0; k0 < K; k0 += BK) {
        // Load 128x16 A tile and 128x16 B tile, transposed into smem.
#pragma unroll
        for (int i = 0; i < 2; i++) {
            int id = tid + i * 256;        // 0..511 float4 ids
            int row = id >> 2;             // 0..127
            int col = (id & 3) << 2;       // 0,4,8,12
            float4 va = *(const float4*)(A + (size_t)(m0 + row) * K + (k0 + col));
            As[col + 0][row] = va.x;
            As[col + 1][row] = va.y;
            As[col + 2][row] = va.z;
            As[col + 3][row] = va.w;
            float4 vb = *(const float4*)(Bmat + (size_t)(n0 + row) * K + (k0 + col));
            Bs[col + 0][row] = vb.x;
            Bs[col + 1][row] = vb.y;
            Bs[col + 2][row] = vb.z;
            Bs[col + 3][row] = vb.w;
        }
        __syncthreads();

#pragma unroll
        for (int kk = 0; kk < BK; kk++) {
            float a[8], b[8];
#pragma unroll
            for (int i = 0; i < 8; i++) a[i] = As[kk][ty * 8 + i];
#pragma unroll
            for (int j = 0; j < 8; j++) b[j] = Bs[kk][tx * 8 + j];
#pragma unroll
            for (int i = 0; i < 8; i++)
#pragma unroll
                for (int j = 0; j < 8; j++) acc[i][j] += a[i] * b[j];
        }
        __syncthreads();
    }

    // Epilogue
#pragma unroll
    for (int i = 0; i < 8; i++) {
        int m = m0 + ty * 8 + i;
#pragma unroll
        for (int j = 0; j < 8; j++) {
            int n = n0 + tx * 8 + j;
            float v = acc[i][j];
            if (MODE == 0) {
                // n in [0, 3E): split into q/k/v, scatter to [B,H,T,D]
                int which = n / E_;
                int e = n - which * E_;
                int h = e / D_;
                int d = e - h * D_;
                int b = m / T_;
                int t = m - b * T_;
                float* dst = (which == 0) ? g_q : (which == 1) ? g_k : g_v;
                dst[(((size_t)b * H_ + h) * T_ + t) * D_ + d] = v;
            } else {
                C[(size_t)m * N + n] = v;
            }
        }
    }
}

// ============================================================================
// Causal flash attention: 1 thread = 1 query row. 128 query rows per block,
// 64-key K/V tiles in smem. Online softmax with rare-branch max rescale.
// Reads g_q/g_k/g_v [B,H,T,D], writes g_att [B*T, E] (head-reassembled).
// ============================================================================
#define QB 128
#define KB 64
#define DP (D_ + 4)   // 68 floats: 16B-aligned rows, odd-ish banking

__global__ void __launch_bounds__(128) attn_kernel() {
    __shared__ float Ks[KB][DP];
    __shared__ float Vs[KB][DP];

    const int tid = threadIdx.x;
    const int bh = blockIdx.y;             // b*H + h
    const int q0 = blockIdx.x * QB;
    const int r = q0 + tid;                // this thread's query row

    // Load my q row into registers
    const float* qptr = g_q + ((size_t)bh * T_ + r) * D_;
    float q[D_];
#pragma unroll
    for (int i = 0; i < D_ / 4; i++) {
        float4 v = *(const float4*)(qptr + 4 * i);
        q[4 * i + 0] = v.x;
        q[4 * i + 1] = v.y;
        q[4 * i + 2] = v.z;
        q[4 * i + 3] = v.w;
    }

    float acc[D_];
#pragma unroll
    for (int d = 0; d < D_; d++) acc[d] = 0.0f;
    float mrow = __int_as_float(0xff800000);   // -inf
    float lrow = 0.0f;
    const float scale = 0.125f;                // 1/sqrt(64)

    const float* kbase = g_k + (size_t)bh * T_ * D_;
    const float* vbase = g_v + (size_t)bh * T_ * D_;

    const int ntiles = (q0 + QB) / KB;         // causal: only tiles with j0 < q0+QB
    for (int kt = 0; kt < ntiles; kt++) {
        const int j0 = kt * KB;

        // Cooperative load of 64x64 K and V tiles (8 float4 each per thread)
#pragma unroll
        for (int i = 0; i < 8; i++) {
            int f4 = tid + i * 128;            // 0..1023
            int row = f4 >> 4;                 // 0..63
            int col = (f4 & 15) << 2;          // 0..60
            *(float4*)&Ks[row][col] = *(const float4*)(kbase + (size_t)(j0 + row) * D_ + col);
            *(float4*)&Vs[row][col] = *(const float4*)(vbase + (size_t)(j0 + row) * D_ + col);
        }
        __syncthreads();

        int jmax = r - j0 + 1;                 // number of causally-valid keys
        if (jmax > KB) jmax = KB;
        for (int j = 0; j < jmax; j++) {
            const float4* kr = (const float4*)&Ks[j][0];
            float s0 = 0.f, s1 = 0.f, s2 = 0.f, s3 = 0.f;
#pragma unroll
            for (int i = 0; i < 16; i++) {
                float4 kv = kr[i];
                s0 += q[4 * i + 0] * kv.x;
                s1 += q[4 * i + 1] * kv.y;
                s2 += q[4 * i + 2] * kv.z;
                s3 += q[4 * i + 3] * kv.w;
            }
            float s = ((s0 + s1) + (s2 + s3)) * scale;

            if (s > mrow) {
                // rare after warmup (~ln(T) times per row); -inf start handled:
                // __expf(-inf)=0 zeroes the (already zero) state.
                float corr = __expf(mrow - s);
#pragma unroll
                for (int d = 0; d < D_; d++) acc[d] *= corr;
                lrow *= corr;
                mrow = s;
            }
            float p = __expf(s - mrow);
            lrow += p;

            const float4* vr = (const float4*)&Vs[j][0];
#pragma unroll
            for (int i = 0; i < 16; i++) {
                float4 vv = vr[i];
                acc[4 * i + 0] += p * vv.x;
                acc[4 * i + 1] += p * vv.y;
                acc[4 * i + 2] += p * vv.z;
                acc[4 * i + 3] += p * vv.w;
            }
        }
        __syncthreads();
    }

    // Write normalized output, reassembled as [B*T, E] row-major
    const float inv = 1.0f / lrow;
    const int b = bh / H_;
    const int h = bh - b * H_;
    float* optr = g_att + ((size_t)(b * T_ + r)) * E_ + h * D_;
#pragma unroll
    for (int i = 0; i < 16; i++) {
        float4 o;
        o.x = acc[4 * i + 0] * inv;
        o.y = acc[4 * i + 1] * inv;
        o.z = acc[4 * i + 2] * inv;
        o.w = acc[4 * i + 3] * inv;
        *(float4*)(optr + 4 * i) = o;
    }
}

// ============================================================================
// Launch
// ============================================================================
extern "C" void kernel_launch(void* const* d_in, const int* in_sizes, int n_in,
                              void* d_out, int out_size) {
    const float* x = (const float*)d_in[0];        // [B,T,E]
    const float* w_qkv = (const float*)d_in[1];    // [3E,E]
    const float* w_proj = (const float*)d_in[2];   // [E,E]
    float* out = (float*)d_out;                    // [B,T,E]

    // 1) QKV projection + split/scatter into [B,H,T,D] q/k/v
    {
        dim3 grid(3 * E_ / BN, BT_ / BM);
        sgemm_nt<0, 3 * E_, E_><<<grid, 256>>>(x, w_qkv, nullptr);
    }

    // 2) Causal flash attention -> g_att [B*T, E]
    {
        dim3 grid(T_ / QB, B_ * H_);
        attn_kernel<<<grid, 128>>>();
    }

    // 3) Output projection -> d_out
    {
        dim3 grid(E_ / BN, BT_ / BM);
        sgemm_nt<1, E_, E_><<<grid, 256>>>(nullptr, w_proj, out);
    }
}